// round 11
// baseline (speedup 1.0000x reference)
#include <cuda_runtime.h>
#include <math.h>

typedef unsigned long long u64;

// ---- packed f32x2 helpers ----
__device__ __forceinline__ u64 pk2(float lo, float hi) {
    u64 r; asm("mov.b64 %0,{%1,%2};" : "=l"(r) : "f"(lo), "f"(hi)); return r;
}
__device__ __forceinline__ void upk2(float& lo, float& hi, u64 v) {
    asm("mov.b64 {%0,%1},%2;" : "=f"(lo), "=f"(hi) : "l"(v));
}
__device__ __forceinline__ u64 fma2(u64 a, u64 b, u64 c) {
    u64 d; asm("fma.rn.f32x2 %0,%1,%2,%3;" : "=l"(d) : "l"(a), "l"(b), "l"(c)); return d;
}
__device__ __forceinline__ u64 mul2(u64 a, u64 b) {
    u64 d; asm("mul.rn.f32x2 %0,%1,%2;" : "=l"(d) : "l"(a), "l"(b)); return d;
}

// Coefficient tensor, DUPLICATED layout: row (i*4+w) has 24 floats =
// 12 u64 lanes; u64 slot j (j=0..8) holds (A[i][w][j], A[i][w][j]); 9..11 pad.
__device__ float g_Ad[9 * 4 * 24];

// ---------------------------------------------------------------------------
// Fast precompute kernel: 256 threads = (amp i = tid%16, column j = tid/16),
// gates via __shfl_xor_sync; writes the duplicated coefficient tensor.
// ---------------------------------------------------------------------------
__global__ void precompute_A_fast_kernel(const float* __restrict__ vp) {
    __shared__ float vc[24], vs[24];
    __shared__ float Ur[16][16], Ui[16][16];
    __shared__ float ReO[4][16][16];

    const int tid = threadIdx.x;
    const int i   = tid & 15;
    const int j   = tid >> 4;

    if (tid < 24) {
        float ss, cc;
        __sincosf(vp[tid] * 0.5f, &ss, &cc);
        vc[tid] = cc;
        vs[tid] = ss;
    }
    __syncthreads();

    float ar = (i == j) ? 1.0f : 0.0f;
    float ai = 0.0f;

#pragma unroll
    for (int l = 0; l < 3; l++) {
        const float* lc = vc + l * 8;
        const float* ls = vs + l * 8;
#pragma unroll
        for (int k = 0; k < 4; k++) {
            const int M = 8 >> k;
            const float cy = lc[k],     sy = ls[k];
            const float cz = lc[k + 1], sz = ls[k + 1];
            // RY
            const float orr = __shfl_xor_sync(0xffffffffu, ar, M);
            const float oii = __shfl_xor_sync(0xffffffffu, ai, M);
            const float sgn = (i & M) ? sy : -sy;
            ar = fmaf(sgn, orr, cy * ar);
            ai = fmaf(sgn, oii, cy * ai);
            // RZ
            const float sg = (i & M) ? -sz : sz;
            const float rr = ar, im = ai;
            ar = fmaf(sg, im, cz * rr);
            ai = fmaf(-sg, rr, cz * im);
        }
#pragma unroll
        for (int k = 0; k < 4; k++) {
            const int CM = 8 >> k;
            const int TM = (k == 3) ? 8 : (4 >> k);
            const float orr = __shfl_xor_sync(0xffffffffu, ar, TM);
            const float oii = __shfl_xor_sync(0xffffffffu, ai, TM);
            if (i & CM) { ar = orr; ai = oii; }
        }
    }

    Ur[i][j] = ar;
    Ui[i][j] = ai;
    __syncthreads();

    {
        const int p = tid >> 4;
        const int q = tid & 15;
        float acc[4] = {0.0f, 0.0f, 0.0f, 0.0f};
#pragma unroll
        for (int k = 0; k < 16; k++) {
            const float t = Ur[k][p] * Ur[k][q] + Ui[k][p] * Ui[k][q];
#pragma unroll
            for (int w = 0; w < 4; w++)
                acc[w] += (k & (8 >> w)) ? -t : t;
        }
#pragma unroll
        for (int w = 0; w < 4; w++) ReO[w][p][q] = acc[w];
    }
    __syncthreads();

    // Duplicated write: logical entry t = row*12 + a34 -> floats 2*a34, 2*a34+1
    for (int t = tid; t < 432; t += 256) {
        const int row = t / 12;          // i*4 + w
        const int w   = row & 3;
        const int a12 = row >> 2;
        const int a34 = t % 12;
        float val = 0.0f;
        if (a34 < 9) {
            const int a0 = a12 / 3, a1 = a12 % 3;
            const int a2 = a34 / 3, a3 = a34 % 3;
            const int zm = (a0 == 1 ? 8 : 0) | (a1 == 1 ? 4 : 0) | (a2 == 1 ? 2 : 0) | (a3 == 1 ? 1 : 0);
            const int xm = (a0 == 2 ? 8 : 0) | (a1 == 2 ? 4 : 0) | (a2 == 2 ? 2 : 0) | (a3 == 2 ? 1 : 0);
            float acc = 0.0f;
#pragma unroll
            for (int p = 0; p < 16; p++) {
                const float v = ReO[w][p][p ^ xm];
                acc += (__popc(p & zm) & 1) ? -v : v;
            }
            val = acc * 0.0625f;
        }
        g_Ad[row * 24 + 2 * a34]     = val;
        g_Ad[row * 24 + 2 * a34 + 1] = val;
    }
}

// ---------------------------------------------------------------------------
// Main fused kernel: one block per 4 IMAGES, image-PAIR-packed FFMA2
// contraction against the pre-duplicated A, warp-GEMM logits, log_softmax.
// ---------------------------------------------------------------------------
__global__ __launch_bounds__(224, 4) void quanv_fused11_kernel(
    const float* __restrict__ x,     // (B,1,28,28)
    const float* __restrict__ W,     // (10,784)
    const float* __restrict__ bias,  // (10,)
    float* __restrict__ out,         // (B,10)
    int B)
{
    const int b0   = 4 * blockIdx.x;
    const int tid  = threadIdx.x;
    const int warp = tid >> 5;
    const int lane = tid & 31;

    __shared__ __align__(16) float sA[9 * 4 * 24];
    __shared__ __align__(16) float4 feats[4][196];
    __shared__ float slog[40];
    __shared__ float slse[4];

    for (int i = tid; i < 9 * 4 * 24; i += 224)
        sA[i] = g_Ad[i];
    __syncthreads();

    if (tid < 196) {
        const int r14 = tid / 14;
        const int c14 = tid % 14;
        const int off = (2 * r14) * 28 + 2 * c14;

        const u64 ONE2 = 0x3F8000003F800000ull;   // (1.0f, 1.0f)

        // Packed angles per image pair pr: lanes = (img 2pr, img 2pr+1)
        u64 C0[2], S0[2], C1[2], S1[2], C2[2], S2[2], C3[2], S3[2];
#pragma unroll
        for (int pr = 0; pr < 2; pr++) {
            float c0a, s0a, c1a, s1a, c2a, s2a, c3a, s3a;
            float c0b, s0b, c1b, s1b, c2b, s2b, c3b, s3b;
            {
                int b = b0 + 2 * pr;
                if (b >= B) b = B - 1;
                const float* xb = x + (size_t)b * 784;
                const float2 t2 = *reinterpret_cast<const float2*>(xb + off);
                const float2 d2 = *reinterpret_cast<const float2*>(xb + off + 28);
                __sincosf(t2.x, &s0a, &c0a);
                __sincosf(t2.y, &s1a, &c1a);
                __sincosf(d2.x, &s2a, &c2a);
                __sincosf(d2.y, &s3a, &c3a);
            }
            {
                int b = b0 + 2 * pr + 1;
                if (b >= B) b = B - 1;
                const float* xb = x + (size_t)b * 784;
                const float2 t2 = *reinterpret_cast<const float2*>(xb + off);
                const float2 d2 = *reinterpret_cast<const float2*>(xb + off + 28);
                __sincosf(t2.x, &s0b, &c0b);
                __sincosf(t2.y, &s1b, &c1b);
                __sincosf(d2.x, &s2b, &c2b);
                __sincosf(d2.y, &s3b, &c3b);
            }
            C0[pr] = pk2(c0a, c0b); S0[pr] = pk2(s0a, s0b);
            C1[pr] = pk2(c1a, c1b); S1[pr] = pk2(s1a, s1b);
            C2[pr] = pk2(c2a, c2b); S2[pr] = pk2(s2a, s2b);
            C3[pr] = pk2(c3a, c3b); S3[pr] = pk2(s3a, s3b);
        }

        u64 e2[2][4];
#pragma unroll
        for (int pr = 0; pr < 2; pr++)
#pragma unroll
            for (int w = 0; w < 4; w++) e2[pr][w] = 0ull;

#pragma unroll
        for (int i = 0; i < 9; i++) {
            const int iu = i / 3, iv = i % 3;
            u64 ga2[2];
#pragma unroll
            for (int pr = 0; pr < 2; pr++) {
                const u64 u2 = (iu == 0) ? ONE2 : (iu == 1 ? C0[pr] : S0[pr]);
                const u64 v2 = (iv == 0) ? ONE2 : (iv == 1 ? C1[pr] : S1[pr]);
                ga2[pr] = (iu == 0) ? v2 : ((iv == 0) ? u2 : mul2(u2, v2));
            }
#pragma unroll
            for (int w = 0; w < 4; w++) {
                const ulonglong2* rowq =
                    reinterpret_cast<const ulonglong2*>(&sA[(i * 4 + w) * 24]);
                const ulonglong2 q0 = rowq[0];   // a0 a1
                const ulonglong2 q1 = rowq[1];   // a2 a3
                const ulonglong2 q2 = rowq[2];   // a4 a5
                const ulonglong2 q3 = rowq[3];   // a6 a7
                const ulonglong2 q4 = rowq[4];   // a8 pad
#pragma unroll
                for (int pr = 0; pr < 2; pr++) {
                    u64 m0 = fma2(q0.y, C3[pr], q0.x);
                    m0 = fma2(q1.x, S3[pr], m0);
                    u64 m1 = fma2(q2.x, C3[pr], q1.y);
                    m1 = fma2(q2.y, S3[pr], m1);
                    u64 m2 = fma2(q3.y, C3[pr], q3.x);
                    m2 = fma2(q4.x, S3[pr], m2);
                    u64 t = fma2(m1, C2[pr], m0);
                    t = fma2(m2, S2[pr], t);
                    e2[pr][w] = fma2(ga2[pr], t, e2[pr][w]);
                }
            }
        }

        // Unpack: lane0 -> image 2pr, lane1 -> image 2pr+1
#pragma unroll
        for (int pr = 0; pr < 2; pr++) {
            float ea[4], eb[4];
#pragma unroll
            for (int w = 0; w < 4; w++) upk2(ea[w], eb[w], e2[pr][w]);
            feats[2 * pr][tid]     = make_float4(ea[0], ea[1], ea[2], ea[3]);
            feats[2 * pr + 1][tid] = make_float4(eb[0], eb[1], eb[2], eb[3]);
        }
    }
    __syncthreads();

    // ---- warp-GEMM logits: 40 tasks (img,class) over 7 warps ----
#pragma unroll
    for (int r = 0; r < 6; r++) {
        const int task = warp + 7 * r;
        if (task < 40) {
            const int img = task / 10;
            const int c   = task % 10;
            const float* wrow = W + c * 784;
            float acc = 0.0f;
#pragma unroll
            for (int k = 0; k < 6; k++) {
                const int p = 32 * k + lane;
                const float4 fv = feats[img][p];
                const float4 wv = *reinterpret_cast<const float4*>(wrow + 4 * p);
                acc = fmaf(fv.x, wv.x, acc);
                acc = fmaf(fv.y, wv.y, acc);
                acc = fmaf(fv.z, wv.z, acc);
                acc = fmaf(fv.w, wv.w, acc);
            }
            if (lane < 4) {
                const int p = 192 + lane;
                const float4 fv = feats[img][p];
                const float4 wv = *reinterpret_cast<const float4*>(wrow + 4 * p);
                acc = fmaf(fv.x, wv.x, acc);
                acc = fmaf(fv.y, wv.y, acc);
                acc = fmaf(fv.z, wv.z, acc);
                acc = fmaf(fv.w, wv.w, acc);
            }
#pragma unroll
            for (int off = 16; off > 0; off >>= 1)
                acc += __shfl_xor_sync(0xffffffffu, acc, off);
            if (lane == 0) slog[task] = acc + bias[c];
        }
    }
    __syncthreads();

    if (tid < 4) {
        const float* l = slog + 10 * tid;
        float mx = l[0];
#pragma unroll
        for (int c = 1; c < 10; c++) mx = fmaxf(mx, l[c]);
        float se = 0.0f;
#pragma unroll
        for (int c = 0; c < 10; c++) se += expf(l[c] - mx);
        slse[tid] = mx + logf(se);
    }
    __syncthreads();

    if (tid < 40) {
        const int img = tid / 10;
        const int b = b0 + img;
        if (b < B)
            out[(size_t)b * 10 + (tid % 10)] = slog[tid] - slse[img];
    }
}

extern "C" void kernel_launch(void* const* d_in, const int* in_sizes, int n_in,
                              void* d_out, int out_size) {
    const float* x    = (const float*)d_in[0];   // (B,1,28,28)
    const float* vp   = (const float*)d_in[1];   // (3,8)
    const float* W    = (const float*)d_in[2];   // (10,784)
    const float* bias = (const float*)d_in[3];   // (10,)
    float* out = (float*)d_out;

    const int B = in_sizes[0] / 784;
    precompute_A_fast_kernel<<<1, 256>>>(vp);
    quanv_fused11_kernel<<<(B + 3) / 4, 224>>>(x, W, bias, out, B);
}